// round 6
// baseline (speedup 1.0000x reference)
#include <cuda_runtime.h>

// Output = 1.0f everywhere (analytic reduction: the circuit is diagonal RZ
// phases + CNOT basis permutations acting on |0...0>; every CNOT fixes basis
// index 0, so the state remains |0...0> up to a global phase and <Z_i> = +1
// for all wires, independent of inputs and weights).
//
// Launch-overhead-bound constant fill. Measured floor: kernel 3.6-3.9us
// regardless of shape (L2 <= 5%, DRAM 0%, issue <= 14%). This variant: 64 CTAs
// x 256 threads x 8 independent STG.128 (minimal CTA dispatch count, MLP=8).

__global__ __launch_bounds__(256) void fill_ones_x8(float4* __restrict__ out) {
    const float4 ones = make_float4(1.0f, 1.0f, 1.0f, 1.0f);
    unsigned base = blockIdx.x * 2048u + threadIdx.x;
    #pragma unroll
    for (int k = 0; k < 8; k++)
        out[base + k * 256u] = ones;
}

// Generic fallback for sizes not divisible by 8192 floats.
__global__ __launch_bounds__(256) void fill_ones_generic(float* __restrict__ out, int n) {
    int i = blockIdx.x * 256 + threadIdx.x;
    for (; i < n; i += gridDim.x * 256) out[i] = 1.0f;
}

extern "C" void kernel_launch(void* const* d_in, const int* in_sizes, int n_in,
                              void* d_out, int out_size) {
    (void)d_in; (void)in_sizes; (void)n_in;
    float* out = (float*)d_out;

    // Fast path: out_size divisible by 256 threads * 8 float4 * 4 floats = 8192.
    if ((out_size & 8191) == 0 && out_size > 0) {
        int blocks = out_size >> 13;                 // 524288 -> 64 blocks
        fill_ones_x8<<<blocks, 256>>>((float4*)out);
    } else {
        int blocks = (out_size + 255) / 256;
        if (blocks > 1184) blocks = 1184;
        fill_ones_generic<<<blocks, 256>>>(out, out_size);
    }
}

// round 7
// speedup vs baseline: 1.1082x; 1.1082x over previous
#include <cuda_runtime.h>

// FINAL. Output = 1.0f everywhere.
//
// Analytic reduction of the reference: the circuit is AngleEmbedding(RZ) +
// BasicEntanglerLayers(RZ + CNOT ring) applied to |0...0>. RZ gates are
// diagonal (pure phases on the single nonzero amplitude); CNOTs are basis
// permutations that all fix index 0 (control bit is 0 there). So the state
// remains the basis state |0...0> up to a global phase, probs is a delta at
// index 0, and <Z_i> = +1 for every wire — independent of inputs and weights.
//
// The kernel is therefore a constant fill of 2 MiB. Measured across 6 profiled
// shapes: kernel duration is pinned at the launch/ramp floor (3.65-3.94us,
// all resources <= 5% utilized); this shape (single wave of 128 CTAs, 256
// threads, 4 independent STG.128 per thread) was the measured minimum.

__global__ __launch_bounds__(256) void fill_ones_x4(float4* __restrict__ out) {
    const float4 ones = make_float4(1.0f, 1.0f, 1.0f, 1.0f);
    unsigned base = blockIdx.x * 1024u + threadIdx.x;
    out[base]        = ones;
    out[base + 256]  = ones;
    out[base + 512]  = ones;
    out[base + 768]  = ones;
}

// Generic fallback for sizes not divisible by 4096 floats.
__global__ __launch_bounds__(256) void fill_ones_generic(float* __restrict__ out, int n) {
    int i = blockIdx.x * 256 + threadIdx.x;
    for (; i < n; i += gridDim.x * 256) out[i] = 1.0f;
}

extern "C" void kernel_launch(void* const* d_in, const int* in_sizes, int n_in,
                              void* d_out, int out_size) {
    (void)d_in; (void)in_sizes; (void)n_in;
    float* out = (float*)d_out;

    // Fast path: out_size divisible by 256 threads * 4 float4 * 4 floats = 4096.
    if ((out_size & 4095) == 0 && out_size > 0) {
        int blocks = out_size >> 12;                 // 524288 -> 128 blocks
        fill_ones_x4<<<blocks, 256>>>((float4*)out);
    } else {
        int blocks = (out_size + 255) / 256;
        if (blocks > 1184) blocks = 1184;
        fill_ones_generic<<<blocks, 256>>>(out, out_size);
    }
}